// round 14
// baseline (speedup 1.0000x reference)
#include <cuda_runtime.h>
#include <cuda_fp16.h>
#include <cstdint>

#define N_NODES 8192
#define F_IN    1024
#define F_OUT   512

// ---------------- device scratch ----------------
__device__ float    g_S [N_NODES * F_OUT];     // seq_fts fp32 (for k2/k1b)
// B operand: S in fp16 m16n8k16 fragment-major (for K5F)
__device__ unsigned g_Bh[(size_t)512 * 32 * 32 * 4];            // 8.4 MB
__device__ float    g_f1[N_NODES];
__device__ float    g_f2[N_NODES];
__device__ float    g_f2max;

// ---------------- helpers ----------------
__device__ __forceinline__ float fast_exp(float x) {
    float t = x * 1.4426950408889634f;
    t = fminf(fmaxf(t, -126.0f), 126.0f);
    float fi = rintf(t);
    float f  = t - fi;
    float p  =          1.5403530393381609e-4f;
    p = fmaf(p, f, 1.3333558146428443e-3f);
    p = fmaf(p, f, 9.6181291076284772e-3f);
    p = fmaf(p, f, 5.5504108664821580e-2f);
    p = fmaf(p, f, 2.4022650695910071e-1f);
    p = fmaf(p, f, 6.9314718055994531e-1f);
    p = fmaf(p, f, 1.0f);
    int e = (int)fi;
    return p * __int_as_float((e + 127) << 23);
}

__device__ __forceinline__ void mma_f16(float* d, const unsigned* a, const unsigned* b) {
    asm volatile(
        "mma.sync.aligned.m16n8k16.row.col.f32.f16.f16.f32 "
        "{%0,%1,%2,%3}, {%4,%5,%6,%7}, {%8,%9}, {%0,%1,%2,%3};"
        : "+f"(d[0]), "+f"(d[1]), "+f"(d[2]), "+f"(d[3])
        : "r"(a[0]), "r"(a[1]), "r"(a[2]), "r"(a[3]), "r"(b[0]), "r"(b[1]));
}

__device__ __forceinline__ unsigned h2bits(float lo, float hi) {
    __half2 h = __floats2half2_rn(lo, hi);   // low 16 bits <- lo
    return *(unsigned*)&h;
}

// ---------------- K1: seq_fts = x @ seq_W.T (fp16 m16n8k16) -----------------
__global__ __launch_bounds__(256) void k1_seqfts(const float* __restrict__ X,
                                                 const float* __restrict__ W) {
    __shared__ unsigned As[128][20];
    __shared__ unsigned Bs[64][20];
    const int tid = threadIdx.x;
    const int m0 = blockIdx.y * 128;
    const int n0 = blockIdx.x * 64;
    const int warp = tid >> 5, lane = tid & 31;
    const int grp = lane >> 2, tig = lane & 3;
    const int wm = warp & 3, wn = warp >> 2;
    const int lr = tid >> 3;
    const int lc = (tid & 7) << 2;
    const int uc = (tid & 7) << 1;

    float d[2][4][4];
#pragma unroll
    for (int i = 0; i < 2; i++)
#pragma unroll
        for (int j = 0; j < 4; j++)
#pragma unroll
            for (int q = 0; q < 4; q++) d[i][j][q] = 0.0f;

    for (int k0 = 0; k0 < F_IN; k0 += 32) {
#pragma unroll
        for (int p = 0; p < 4; p++) {
            float4 v = *(const float4*)&X[(size_t)(m0 + lr + p * 32) * F_IN + k0 + lc];
            As[lr + p * 32][uc]     = h2bits(v.x, v.y);
            As[lr + p * 32][uc + 1] = h2bits(v.z, v.w);
        }
#pragma unroll
        for (int p = 0; p < 2; p++) {
            float4 v = *(const float4*)&W[(size_t)(n0 + lr + p * 32) * F_IN + k0 + lc];
            Bs[lr + p * 32][uc]     = h2bits(v.x, v.y);
            Bs[lr + p * 32][uc + 1] = h2bits(v.z, v.w);
        }
        __syncthreads();
#pragma unroll
        for (int kt = 0; kt < 2; kt++) {
            unsigned ah[2][4];
#pragma unroll
            for (int mt = 0; mt < 2; mt++) {
                int rb = wm * 32 + mt * 16;
                ah[mt][0] = As[rb + grp][kt * 8 + tig];
                ah[mt][1] = As[rb + grp + 8][kt * 8 + tig];
                ah[mt][2] = As[rb + grp][kt * 8 + tig + 4];
                ah[mt][3] = As[rb + grp + 8][kt * 8 + tig + 4];
            }
            unsigned bh[4][2];
#pragma unroll
            for (int nt = 0; nt < 4; nt++) {
                int cb = wn * 32 + nt * 8;
                bh[nt][0] = Bs[cb + grp][kt * 8 + tig];
                bh[nt][1] = Bs[cb + grp][kt * 8 + tig + 4];
            }
#pragma unroll
            for (int mt = 0; mt < 2; mt++)
#pragma unroll
                for (int nt = 0; nt < 4; nt++)
                    mma_f16(d[mt][nt], ah[mt], bh[nt]);
        }
        __syncthreads();
    }
#pragma unroll
    for (int mt = 0; mt < 2; mt++)
#pragma unroll
        for (int nt = 0; nt < 4; nt++) {
            int r = m0 + wm * 32 + mt * 16 + grp;
            int c = n0 + wn * 32 + nt * 8 + tig * 2;
            size_t i00 = (size_t)r * F_OUT + c;
            size_t i10 = (size_t)(r + 8) * F_OUT + c;
            g_S[i00]     = d[mt][nt][0];
            g_S[i00 + 1] = d[mt][nt][1];
            g_S[i10]     = d[mt][nt][2];
            g_S[i10 + 1] = d[mt][nt][3];
        }
}

// ---------------- K1b: repack S -> fp16 B fragments (g_Bh) ------------------
__global__ __launch_bounds__(256) void k1b_repack() {
    __shared__ float tS[16][520];
    const int k16 = blockIdx.x;
    const int tid = threadIdx.x;
#pragma unroll
    for (int i = 0; i < 8; i++) {
        int idx = tid + i * 256;
        int row = idx >> 7, c4 = (idx & 127) << 2;
        *(float4*)&tS[row][c4] = *(const float4*)&g_S[(size_t)(k16 * 16 + row) * F_OUT + c4];
    }
    __syncthreads();
#pragma unroll
    for (int i = 0; i < 4; i++) {
        int item = tid + i * 256;
        int p = item >> 5, lane = item & 31;
        int gb = lane >> 2, tb = lane & 3;
        int n0 = p * 16 + gb, n1 = n0 + 8;
        int k0 = 2 * tb;
        uint4 q;
        q.x = h2bits(tS[k0][n0],     tS[k0 + 1][n0]);
        q.y = h2bits(tS[k0 + 8][n0], tS[k0 + 9][n0]);
        q.z = h2bits(tS[k0][n1],     tS[k0 + 1][n1]);
        q.w = h2bits(tS[k0 + 8][n1], tS[k0 + 9][n1]);
        ((uint4*)g_Bh)[((size_t)k16 * 32 + p) * 32 + lane] = q;
    }
}

// ---------------- K2: f1/f2 projections -------------------------------------
__global__ __launch_bounds__(256) void k2_fvec(const float* __restrict__ f1w,
                                               const float* __restrict__ f1b,
                                               const float* __restrict__ f2w,
                                               const float* __restrict__ f2b) {
    int row = blockIdx.x * 8 + (threadIdx.x >> 5);
    int lane = threadIdx.x & 31;
    const float* Sr = g_S + (size_t)row * F_OUT;
    float s1 = 0.f, s2 = 0.f;
    for (int c = lane; c < F_OUT; c += 32) {
        float v = Sr[c];
        s1 = fmaf(v, f1w[c], s1);
        s2 = fmaf(v, f2w[c], s2);
    }
#pragma unroll
    for (int o = 16; o > 0; o >>= 1) {
        s1 += __shfl_xor_sync(0xffffffff, s1, o);
        s2 += __shfl_xor_sync(0xffffffff, s2, o);
    }
    if (lane == 0) {
        g_f1[row] = s1 + f1b[0];
        g_f2[row] = s2 + f2b[0];
    }
}

// ---------------- K2b: global max of f2 --------------------------------------
__global__ void k2b_f2max() {
    __shared__ float mx[256];
    float m = -1e30f;
    for (int i = threadIdx.x; i < N_NODES; i += 256) m = fmaxf(m, g_f2[i]);
    mx[threadIdx.x] = m;
    __syncthreads();
    for (int s = 128; s > 0; s >>= 1) {
        if (threadIdx.x < s) mx[threadIdx.x] = fmaxf(mx[threadIdx.x], mx[threadIdx.x + s]);
        __syncthreads();
    }
    if (threadIdx.x == 0) g_f2max = mx[0];
}

// ---------------- K5F: fused pgen + Z + RWR count + GEMM + epilogue ---------
// BM=64, BN=512 (full N, no pgen duplication). 512 thr / 16 warps.
// pgen role: warp -> (k16 kq = warp>>2, m16p = warp&3); each lane makes one
// A-frag uint4 per slab, STS.128 into double-buffered PA (8KB/stage).
// GEMM role: warp tile 32x64 (wm=warp>>3, wn=warp&7); B streamed from g_Bh.
// One __syncthreads per slab.
__global__ __launch_bounds__(512, 1) void k5f(const float* __restrict__ adj,
                                              const int* __restrict__ adj_ad,
                                              const float* __restrict__ bias,
                                              float* __restrict__ out,
                                              float* __restrict__ out_ri,
                                              int write_ri) {
    __shared__ uint4 PA[2 * 512];        // 16 KB
    __shared__ float sf2[N_NODES];       // 32 KB
    __shared__ float f1s[64];
    __shared__ float zbuf[4][64];
    __shared__ int   cbuf[4][64];
    __shared__ float rzs[64];
    __shared__ float sbias[512];

    const int tid = threadIdx.x;
    const int m0 = blockIdx.x * 64;
    const int warp = tid >> 5, lane = tid & 31;
    const int grp = lane >> 2, tig = lane & 3;
    // GEMM role
    const int wm = warp >> 3, wn = warp & 7;
    // pgen role
    const int kq = warp >> 2, m16p = warp & 3;
    const int r0l = m16p * 16 + grp, r1l = r0l + 8;

    sbias[tid] = bias[tid];
#pragma unroll
    for (int i = 0; i < 4; i++) {
        int e = (tid + i * 512) * 4;
        *(float4*)&sf2[e] = *(const float4*)&g_f2[e];
    }
    if (tid < 64) f1s[tid] = g_f1[m0 + tid];

    const float* a0p = adj + (size_t)(m0 + r0l) * N_NODES;
    const float* a1p = adj + (size_t)(m0 + r1l) * N_NODES;
    const int*   c0p = adj_ad + (size_t)(m0 + r0l) * N_NODES;
    const int*   c1p = adj_ad + (size_t)(m0 + r1l) * N_NODES;

    float2 adjv00, adjv08, adjv10, adjv18;
    int2   adjc00, adjc08, adjc10, adjc18;

#define LOADADJ(sidx) do { \
    const int _cc = ((sidx) * 4 + kq) * 16 + 2 * tig; \
    adjv00 = *(const float2*)(a0p + _cc); adjv08 = *(const float2*)(a0p + _cc + 8); \
    adjv10 = *(const float2*)(a1p + _cc); adjv18 = *(const float2*)(a1p + _cc + 8); \
    adjc00 = *(const int2*)(c0p + _cc);   adjc08 = *(const int2*)(c0p + _cc + 8); \
    adjc10 = *(const int2*)(c1p + _cc);   adjc18 = *(const int2*)(c1p + _cc + 8); \
} while (0)

    LOADADJ(0);
    __syncthreads();      // sf2, f1s, sbias visible

    const float f2m = g_f2max;
    const float f10 = f1s[r0l], f11 = f1s[r1l];
    float t0 = f10 + f2m; t0 = t0 > 0.f ? t0 : 0.2f * t0;
    float t1 = f11 + f2m; t1 = t1 > 0.f ? t1 : 0.2f * t1;
    const float s0 = t0 + 6.0f, s1 = t1 + 6.0f;

    float z0 = 0.f, z1 = 0.f;
    int cnt0 = 0, cnt1 = 0;

#define PEXP(f1v, f2v, av, sv) ({ float _l = (f1v) + (f2v); _l = _l > 0.f ? _l : 0.2f * _l; \
                                  fminf(fast_exp(_l + (av) - (sv)), 60000.0f); })
#define CNT2(v) (((v).x == 2 || (v).x == 3) + ((v).y == 2 || (v).y == 3))

#define PGEN(sidx, bufi) do { \
    const int _cc = ((sidx) * 4 + kq) * 16 + 2 * tig; \
    float2 _f2a = *(const float2*)&sf2[_cc]; \
    float2 _f2b = *(const float2*)&sf2[_cc + 8]; \
    float e00 = PEXP(f10, _f2a.x, adjv00.x, s0); \
    float e01 = PEXP(f10, _f2a.y, adjv00.y, s0); \
    float e08 = PEXP(f10, _f2b.x, adjv08.x, s0); \
    float e09 = PEXP(f10, _f2b.y, adjv08.y, s0); \
    float e10 = PEXP(f11, _f2a.x, adjv10.x, s1); \
    float e11 = PEXP(f11, _f2a.y, adjv10.y, s1); \
    float e18 = PEXP(f11, _f2b.x, adjv18.x, s1); \
    float e19 = PEXP(f11, _f2b.y, adjv18.y, s1); \
    z0 += (e00 + e01) + (e08 + e09); \
    z1 += (e10 + e11) + (e18 + e19); \
    cnt0 += CNT2(adjc00) + CNT2(adjc08); \
    cnt1 += CNT2(adjc10) + CNT2(adjc18); \
    uint4 _q; \
    _q.x = h2bits(e00, e01); _q.y = h2bits(e10, e11); \
    _q.z = h2bits(e08, e09); _q.w = h2bits(e18, e19); \
    PA[(bufi) * 512 + (kq * 4 + m16p) * 32 + lane] = _q; \
} while (0)

    float d[2][8][4];
#pragma unroll
    for (int mt = 0; mt < 2; mt++)
#pragma unroll
        for (int nt = 0; nt < 8; nt++)
#pragma unroll
            for (int q = 0; q < 4; q++) d[mt][nt][q] = 0.0f;

    // B fragment stream (identical to the R12 k5 path)
    const uint4* qB = (const uint4*)g_Bh + (size_t)(4 * wn) * 32 + lane;
    uint4 bb[4], nb[4];
#pragma unroll
    for (int tt = 0; tt < 4; tt++) bb[tt] = qB[tt * 32];
    const uint4* qn = qB + 1024;

    // prologue pgen
    PGEN(0, 0);
    LOADADJ(1);

    for (int s = 0; s < 128; s++) {
        __syncthreads();          // publish PA[s&1]; PA[(s+1)&1] free
        const int buf = s & 1;

#pragma unroll
        for (int kk = 0; kk < 4; kk++) {
            if (kk == 0 && s + 1 < 128) PGEN(s + 1, buf ^ 1);
            if (kk == 1 && s + 2 < 128) LOADADJ(s + 2);
            if ((kk < 3) || (s < 127)) {
#pragma unroll
                for (int tt = 0; tt < 4; tt++) nb[tt] = qn[tt * 32];
            }
            uint4 av0 = PA[buf * 512 + (kk * 4 + 2 * wm) * 32 + lane];
            uint4 av1 = PA[buf * 512 + (kk * 4 + 2 * wm + 1) * 32 + lane];
#pragma unroll
            for (int tt = 0; tt < 4; tt++) {
                unsigned be[2] = {bb[tt].x, bb[tt].y};
                unsigned bo[2] = {bb[tt].z, bb[tt].w};
                mma_f16(d[0][2 * tt],     (unsigned*)&av0, be);
                mma_f16(d[0][2 * tt + 1], (unsigned*)&av0, bo);
                mma_f16(d[1][2 * tt],     (unsigned*)&av1, be);
                mma_f16(d[1][2 * tt + 1], (unsigned*)&av1, bo);
            }
#pragma unroll
            for (int tt = 0; tt < 4; tt++) bb[tt] = nb[tt];
            qn += 1024;
        }
    }

    // ---- Z / count reduction ----
    z0 += __shfl_xor_sync(0xffffffff, z0, 1);
    z0 += __shfl_xor_sync(0xffffffff, z0, 2);
    z1 += __shfl_xor_sync(0xffffffff, z1, 1);
    z1 += __shfl_xor_sync(0xffffffff, z1, 2);
    cnt0 += __shfl_xor_sync(0xffffffff, cnt0, 1);
    cnt0 += __shfl_xor_sync(0xffffffff, cnt0, 2);
    cnt1 += __shfl_xor_sync(0xffffffff, cnt1, 1);
    cnt1 += __shfl_xor_sync(0xffffffff, cnt1, 2);
    if (tig == 0) {
        zbuf[kq][r0l] = z0;  zbuf[kq][r1l] = z1;
        cbuf[kq][r0l] = cnt0; cbuf[kq][r1l] = cnt1;
    }
    __syncthreads();
    if (tid < 64) {
        float z = (zbuf[0][tid] + zbuf[1][tid]) + (zbuf[2][tid] + zbuf[3][tid]);
        rzs[tid] = 1.0f / z;
        if (write_ri) {
            int c = cbuf[0][tid] + cbuf[1][tid] + cbuf[2][tid] + cbuf[3][tid];
            float k = (float)c;
            float den = 1.0f - 0.25f * k;
            float r0, rn;
            if (den == 0.0f) { r0 = 1.0f; rn = 0.5f; }
            else             { r0 = fabsf(1.0f / den); rn = fabsf(0.5f / den); }
            out_ri[2 * (m0 + tid)]     = r0;
            out_ri[2 * (m0 + tid) + 1] = rn;
        }
    }
    __syncthreads();

    // ---- epilogue: /Z, +bias, ELU ----
#pragma unroll
    for (int mt = 0; mt < 2; mt++) {
        int rl = wm * 32 + mt * 16 + grp;
        float rz0 = rzs[rl], rz1 = rzs[rl + 8];
        int gi = m0 + rl;
#pragma unroll
        for (int nt = 0; nt < 8; nt++) {
            int gf = wn * 64 + nt * 8 + tig * 2;
            float b0 = sbias[gf], b1 = sbias[gf + 1];
            float v;
            v = fmaf(d[mt][nt][0], rz0, b0);
            out[(size_t)gi * F_OUT + gf]           = v > 0.f ? v : fast_exp(v) - 1.0f;
            v = fmaf(d[mt][nt][1], rz0, b1);
            out[(size_t)gi * F_OUT + gf + 1]       = v > 0.f ? v : fast_exp(v) - 1.0f;
            v = fmaf(d[mt][nt][2], rz1, b0);
            out[(size_t)(gi + 8) * F_OUT + gf]     = v > 0.f ? v : fast_exp(v) - 1.0f;
            v = fmaf(d[mt][nt][3], rz1, b1);
            out[(size_t)(gi + 8) * F_OUT + gf + 1] = v > 0.f ? v : fast_exp(v) - 1.0f;
        }
    }
}

// ---------------- launch ----------------
extern "C" void kernel_launch(void* const* d_in, const int* in_sizes, int n_in,
                              void* d_out, int out_size) {
    const float* x      = (const float*)d_in[0];
    const float* adj    = (const float*)d_in[1];
    const int*   adj_ad = (const int*)d_in[2];
    const float* seq_W  = (const float*)d_in[3];
    const float* f1w    = (const float*)d_in[4];
    const float* f1b    = (const float*)d_in[5];
    const float* f2w    = (const float*)d_in[6];
    const float* f2b    = (const float*)d_in[7];
    const float* bias   = (const float*)d_in[8];
    float* out = (float*)d_out;

    k1_seqfts<<<dim3(8, 64), 256>>>(x, seq_W);
    k1b_repack<<<512, 256>>>();
    k2_fvec<<<N_NODES / 8, 256>>>(f1w, f1b, f2w, f2b);
    k2b_f2max<<<1, 256>>>();
    int write_ri = (out_size >= N_NODES * F_OUT + 2 * N_NODES) ? 1 : 0;
    k5f<<<N_NODES / 64, 512>>>(adj, adj_ad, bias, out,
                               out + (size_t)N_NODES * F_OUT, write_ri);
}

// round 15
// speedup vs baseline: 1.2050x; 1.2050x over previous
#include <cuda_runtime.h>
#include <cuda_fp16.h>
#include <cstdint>

#define N_NODES 8192
#define F_IN    1024
#define F_OUT   512
#define NCHUNK  16

// ---------------- device scratch ----------------
__device__ float    g_S [N_NODES * F_OUT];     // seq_fts fp32 (for k2/k1b)
__device__ unsigned g_Bh[(size_t)512 * 32 * 32 * 4];            // 8.4 MB
__device__ unsigned g_Af[(size_t)512 * 512 * 128];              // 134 MB
__device__ float    g_Zpart[NCHUNK][N_NODES];
__device__ int      g_Cpart[NCHUNK][N_NODES];
__device__ float    g_f1[N_NODES];
__device__ float    g_f2[N_NODES];
__device__ unsigned g_f2maxi;                  // ordered-uint encoding of max(f2)

// ---------------- helpers ----------------
__device__ __forceinline__ float fast_exp(float x) {
    float t = x * 1.4426950408889634f;
    t = fminf(fmaxf(t, -126.0f), 126.0f);
    float fi = rintf(t);
    float f  = t - fi;
    float p  =          1.5403530393381609e-4f;
    p = fmaf(p, f, 1.3333558146428443e-3f);
    p = fmaf(p, f, 9.6181291076284772e-3f);
    p = fmaf(p, f, 5.5504108664821580e-2f);
    p = fmaf(p, f, 2.4022650695910071e-1f);
    p = fmaf(p, f, 6.9314718055994531e-1f);
    p = fmaf(p, f, 1.0f);
    int e = (int)fi;
    return p * __int_as_float((e + 127) << 23);
}

__device__ __forceinline__ void mma_f16(float* d, const unsigned* a, const unsigned* b) {
    asm volatile(
        "mma.sync.aligned.m16n8k16.row.col.f32.f16.f16.f32 "
        "{%0,%1,%2,%3}, {%4,%5,%6,%7}, {%8,%9}, {%0,%1,%2,%3};"
        : "+f"(d[0]), "+f"(d[1]), "+f"(d[2]), "+f"(d[3])
        : "r"(a[0]), "r"(a[1]), "r"(a[2]), "r"(a[3]), "r"(b[0]), "r"(b[1]));
}

__device__ __forceinline__ void cp16(void* smem_ptr, const void* gptr) {
    unsigned sa = (unsigned)__cvta_generic_to_shared(smem_ptr);
    asm volatile("cp.async.cg.shared.global [%0], [%1], 16;" :: "r"(sa), "l"(gptr));
}
__device__ __forceinline__ void cp_commit() { asm volatile("cp.async.commit_group;"); }
__device__ __forceinline__ void cp_wait1()  { asm volatile("cp.async.wait_group 1;"); }

__device__ __forceinline__ unsigned h2bits(float lo, float hi) {
    __half2 h = __floats2half2_rn(lo, hi);
    return *(unsigned*)&h;
}

// ordered-uint encode/decode for float atomic max (works for +/- values)
__device__ __forceinline__ unsigned fenc(float v) {
    unsigned b = __float_as_uint(v);
    return (b & 0x80000000u) ? ~b : (b | 0x80000000u);
}
__device__ __forceinline__ float fdec(unsigned e) {
    unsigned b = (e & 0x80000000u) ? (e & 0x7fffffffu) : ~e;
    return __uint_as_float(b);
}

// ---------------- K1: seq_fts = x @ seq_W.T (fp16 m16n8k16) -----------------
__global__ __launch_bounds__(256) void k1_seqfts(const float* __restrict__ X,
                                                 const float* __restrict__ W) {
    // reset f2max accumulator once per launch (k1 precedes k2 in stream order)
    if (blockIdx.x == 0 && blockIdx.y == 0 && threadIdx.x == 0) g_f2maxi = 0u;

    __shared__ unsigned As[128][20];
    __shared__ unsigned Bs[64][20];
    const int tid = threadIdx.x;
    const int m0 = blockIdx.y * 128;
    const int n0 = blockIdx.x * 64;
    const int warp = tid >> 5, lane = tid & 31;
    const int grp = lane >> 2, tig = lane & 3;
    const int wm = warp & 3, wn = warp >> 2;
    const int lr = tid >> 3;
    const int lc = (tid & 7) << 2;
    const int uc = (tid & 7) << 1;

    float d[2][4][4];
#pragma unroll
    for (int i = 0; i < 2; i++)
#pragma unroll
        for (int j = 0; j < 4; j++)
#pragma unroll
            for (int q = 0; q < 4; q++) d[i][j][q] = 0.0f;

    for (int k0 = 0; k0 < F_IN; k0 += 32) {
#pragma unroll
        for (int p = 0; p < 4; p++) {
            float4 v = *(const float4*)&X[(size_t)(m0 + lr + p * 32) * F_IN + k0 + lc];
            As[lr + p * 32][uc]     = h2bits(v.x, v.y);
            As[lr + p * 32][uc + 1] = h2bits(v.z, v.w);
        }
#pragma unroll
        for (int p = 0; p < 2; p++) {
            float4 v = *(const float4*)&W[(size_t)(n0 + lr + p * 32) * F_IN + k0 + lc];
            Bs[lr + p * 32][uc]     = h2bits(v.x, v.y);
            Bs[lr + p * 32][uc + 1] = h2bits(v.z, v.w);
        }
        __syncthreads();
#pragma unroll
        for (int kt = 0; kt < 2; kt++) {
            unsigned ah[2][4];
#pragma unroll
            for (int mt = 0; mt < 2; mt++) {
                int rb = wm * 32 + mt * 16;
                ah[mt][0] = As[rb + grp][kt * 8 + tig];
                ah[mt][1] = As[rb + grp + 8][kt * 8 + tig];
                ah[mt][2] = As[rb + grp][kt * 8 + tig + 4];
                ah[mt][3] = As[rb + grp + 8][kt * 8 + tig + 4];
            }
            unsigned bh[4][2];
#pragma unroll
            for (int nt = 0; nt < 4; nt++) {
                int cb = wn * 32 + nt * 8;
                bh[nt][0] = Bs[cb + grp][kt * 8 + tig];
                bh[nt][1] = Bs[cb + grp][kt * 8 + tig + 4];
            }
#pragma unroll
            for (int mt = 0; mt < 2; mt++)
#pragma unroll
                for (int nt = 0; nt < 4; nt++)
                    mma_f16(d[mt][nt], ah[mt], bh[nt]);
        }
        __syncthreads();
    }
#pragma unroll
    for (int mt = 0; mt < 2; mt++)
#pragma unroll
        for (int nt = 0; nt < 4; nt++) {
            int r = m0 + wm * 32 + mt * 16 + grp;
            int c = n0 + wn * 32 + nt * 8 + tig * 2;
            size_t i00 = (size_t)r * F_OUT + c;
            size_t i10 = (size_t)(r + 8) * F_OUT + c;
            g_S[i00]     = d[mt][nt][0];
            g_S[i00 + 1] = d[mt][nt][1];
            g_S[i10]     = d[mt][nt][2];
            g_S[i10 + 1] = d[mt][nt][3];
        }
}

// ---------------- K1b: repack S -> fp16 B fragments (g_Bh) ------------------
__global__ __launch_bounds__(256) void k1b_repack() {
    __shared__ float tS[16][520];
    const int k16 = blockIdx.x;
    const int tid = threadIdx.x;
#pragma unroll
    for (int i = 0; i < 8; i++) {
        int idx = tid + i * 256;
        int row = idx >> 7, c4 = (idx & 127) << 2;
        *(float4*)&tS[row][c4] = *(const float4*)&g_S[(size_t)(k16 * 16 + row) * F_OUT + c4];
    }
    __syncthreads();
#pragma unroll
    for (int i = 0; i < 4; i++) {
        int item = tid + i * 256;
        int p = item >> 5, lane = item & 31;
        int gb = lane >> 2, tb = lane & 3;
        int n0 = p * 16 + gb, n1 = n0 + 8;
        int k0 = 2 * tb;
        uint4 q;
        q.x = h2bits(tS[k0][n0],     tS[k0 + 1][n0]);
        q.y = h2bits(tS[k0 + 8][n0], tS[k0 + 9][n0]);
        q.z = h2bits(tS[k0][n1],     tS[k0 + 1][n1]);
        q.w = h2bits(tS[k0 + 8][n1], tS[k0 + 9][n1]);
        ((uint4*)g_Bh)[((size_t)k16 * 32 + p) * 32 + lane] = q;
    }
}

// ---------------- K2: f1/f2 projections + f2max (atomic) --------------------
__global__ __launch_bounds__(256) void k2_fvec(const float* __restrict__ f1w,
                                               const float* __restrict__ f1b,
                                               const float* __restrict__ f2w,
                                               const float* __restrict__ f2b) {
    __shared__ float bmax[8];
    int warp = threadIdx.x >> 5;
    int row = blockIdx.x * 8 + warp;
    int lane = threadIdx.x & 31;
    const float* Sr = g_S + (size_t)row * F_OUT;
    float s1 = 0.f, s2 = 0.f;
    for (int c = lane; c < F_OUT; c += 32) {
        float v = Sr[c];
        s1 = fmaf(v, f1w[c], s1);
        s2 = fmaf(v, f2w[c], s2);
    }
#pragma unroll
    for (int o = 16; o > 0; o >>= 1) {
        s1 += __shfl_xor_sync(0xffffffff, s1, o);
        s2 += __shfl_xor_sync(0xffffffff, s2, o);
    }
    float f2v = s2 + f2b[0];
    if (lane == 0) {
        g_f1[row] = s1 + f1b[0];
        g_f2[row] = f2v;
        bmax[warp] = f2v;
    }
    __syncthreads();
    if (threadIdx.x == 0) {
        float m = bmax[0];
#pragma unroll
        for (int i = 1; i < 8; i++) m = fmaxf(m, bmax[i]);
        atomicMax(&g_f2maxi, fenc(m));
    }
}

// ---------------- K4a: pgen + RWR count (fused), grid (16,64) ----------------
__global__ __launch_bounds__(256) void k4a_pgen(const float* __restrict__ adj,
                                                const int* __restrict__ adj_ad) {
    const int tid = threadIdx.x;
    const int warp = tid >> 5, lane = tid & 31;
    const int grp = lane >> 2, tig = lane & 3;
    const int m16 = blockIdx.y * 8 + warp;
    const int r0 = m16 * 16 + grp, r1 = r0 + 8;
    const int kbeg = blockIdx.x * 32;            // 32 k16 per chunk
    const float f2m = fdec(g_f2maxi);
    const float f10 = g_f1[r0], f11 = g_f1[r1];
    float t0 = f10 + f2m; t0 = t0 > 0.f ? t0 : 0.2f * t0;
    float t1 = f11 + f2m; t1 = t1 > 0.f ? t1 : 0.2f * t1;
    const float s0 = t0 + 6.0f, s1 = t1 + 6.0f;
    const float* a0p = adj + (size_t)r0 * N_NODES;
    const float* a1p = adj + (size_t)r1 * N_NODES;
    const int* c0p = adj_ad + (size_t)r0 * N_NODES;
    const int* c1p = adj_ad + (size_t)r1 * N_NODES;
    float z0 = 0.f, z1 = 0.f;
    int cnt0 = 0, cnt1 = 0;
    uint4* dst = (uint4*)g_Af + ((size_t)kbeg * 512 + m16) * 32 + lane;

#define PEXP(f1v, f2v, av, sv) ({ float _l = (f1v) + (f2v); _l = _l > 0.f ? _l : 0.2f * _l; \
                                  fminf(fast_exp(_l + (av) - (sv)), 60000.0f); })
#define CNT2(v) (((v).x == 2 || (v).x == 3) + ((v).y == 2 || (v).y == 3))

    for (int k16 = kbeg; k16 < kbeg + 32; k16++) {
        const int c0 = k16 * 16 + 2 * tig;
        float2 f2a = *(const float2*)&g_f2[c0];
        float2 f2b = *(const float2*)&g_f2[c0 + 8];
        float2 a00 = *(const float2*)(a0p + c0);
        float2 a08 = *(const float2*)(a0p + c0 + 8);
        float2 a10 = *(const float2*)(a1p + c0);
        float2 a18 = *(const float2*)(a1p + c0 + 8);
        int2 q00 = *(const int2*)(c0p + c0);
        int2 q08 = *(const int2*)(c0p + c0 + 8);
        int2 q10 = *(const int2*)(c1p + c0);
        int2 q18 = *(const int2*)(c1p + c0 + 8);
        cnt0 += CNT2(q00) + CNT2(q08);
        cnt1 += CNT2(q10) + CNT2(q18);
        float e00 = PEXP(f10, f2a.x, a00.x, s0);
        float e01 = PEXP(f10, f2a.y, a00.y, s0);
        float e08 = PEXP(f10, f2b.x, a08.x, s0);
        float e09 = PEXP(f10, f2b.y, a08.y, s0);
        float e10 = PEXP(f11, f2a.x, a10.x, s1);
        float e11 = PEXP(f11, f2a.y, a10.y, s1);
        float e18 = PEXP(f11, f2b.x, a18.x, s1);
        float e19 = PEXP(f11, f2b.y, a18.y, s1);
        z0 += (e00 + e01) + (e08 + e09);
        z1 += (e10 + e11) + (e18 + e19);
        uint4 q;
        q.x = h2bits(e00, e01);
        q.y = h2bits(e10, e11);
        q.z = h2bits(e08, e09);
        q.w = h2bits(e18, e19);
        *dst = q;
        dst += 512 * 32;
    }
    z0 += __shfl_xor_sync(0xffffffff, z0, 1);
    z0 += __shfl_xor_sync(0xffffffff, z0, 2);
    z1 += __shfl_xor_sync(0xffffffff, z1, 1);
    z1 += __shfl_xor_sync(0xffffffff, z1, 2);
    cnt0 += __shfl_xor_sync(0xffffffff, cnt0, 1);
    cnt0 += __shfl_xor_sync(0xffffffff, cnt0, 2);
    cnt1 += __shfl_xor_sync(0xffffffff, cnt1, 1);
    cnt1 += __shfl_xor_sync(0xffffffff, cnt1, 2);
    if (tig == 0) {
        g_Zpart[blockIdx.x][r0] = z0;
        g_Zpart[blockIdx.x][r1] = z1;
        g_Cpart[blockIdx.x][r0] = cnt0;
        g_Cpart[blockIdx.x][r1] = cnt1;
    }
}

// ---------------- K4b: RWR finalize ------------------------------------------
__global__ __launch_bounds__(256) void k4b_ri(float* __restrict__ out_ri,
                                              int write_ri) {
    int i = blockIdx.x * 256 + threadIdx.x;
    if (!write_ri || i >= N_NODES) return;
    int c = 0;
#pragma unroll
    for (int p = 0; p < NCHUNK; p++) c += g_Cpart[p][i];
    float k = (float)c;
    float den = 1.0f - 0.25f * k;
    float r0, rn;
    if (den == 0.0f) { r0 = 1.0f; rn = 0.5f; }
    else             { r0 = fabsf(1.0f / den); rn = fabsf(0.5f / den); }
    out_ri[2 * i]     = r0;
    out_ri[2 * i + 1] = rn;
}

// ---------------- K5: GEMM  h = elu(P' @ S / Z' + bias) ---------------------
__global__ __launch_bounds__(512, 1) void k5_gemm(const float* __restrict__ bias,
                                                  float* __restrict__ out) {
    __shared__ unsigned smA[3 * 2048];
    __shared__ float rzs[64];
    __shared__ float sbias[512];

    const int tid = threadIdx.x;
    const int m0 = blockIdx.x * 64;
    const int warp = tid >> 5, lane = tid & 31;
    const int grp = lane >> 2, tig = lane & 3;
    const int wm = warp >> 3, wn = warp & 7;
    const int mB = m0 >> 4;
    const int k16l = tid >> 7, rest = tid & 127;
    const int m16l = rest >> 5, cl = rest & 31;

    sbias[tid] = bias[tid];

    float d[2][8][4];
#pragma unroll
    for (int mt = 0; mt < 2; mt++)
#pragma unroll
        for (int nt = 0; nt < 8; nt++)
#pragma unroll
            for (int q = 0; q < 4; q++) d[mt][nt][q] = 0.0f;

    const uint4* qB = (const uint4*)g_Bh + (size_t)(4 * wn) * 32 + lane;
    uint4 bb[4], nb[4];
#pragma unroll
    for (int tt = 0; tt < 4; tt++) bb[tt] = qB[tt * 32];
    const uint4* qn = qB + 1024;

#pragma unroll
    for (int s = 0; s < 2; s++) {
        const unsigned* src = g_Af + (((size_t)(s * 4 + k16l) * 512) + mB + m16l) * 128 + cl * 4;
        cp16(&smA[s * 2048 + (k16l * 4 + m16l) * 128 + cl * 4], src);
        cp_commit();
    }

    for (int s = 0; s < 128; s++) {
        const int st = s % 3;
        cp_wait1();
        __syncthreads();
        if (s + 2 < 128) {
            const int st2 = (s + 2) % 3;
            const unsigned* src = g_Af + (((size_t)((s + 2) * 4 + k16l) * 512) + mB + m16l) * 128 + cl * 4;
            cp16(&smA[st2 * 2048 + (k16l * 4 + m16l) * 128 + cl * 4], src);
        }
        cp_commit();

#pragma unroll
        for (int kk = 0; kk < 4; kk++) {
            if ((kk < 3) || (s < 127)) {
#pragma unroll
                for (int tt = 0; tt < 4; tt++) nb[tt] = qn[tt * 32];
            }
            uint4 av0 = *(const uint4*)&smA[st * 2048 + (kk * 4 + 2 * wm) * 128 + lane * 4];
            uint4 av1 = *(const uint4*)&smA[st * 2048 + (kk * 4 + 2 * wm + 1) * 128 + lane * 4];
#pragma unroll
            for (int tt = 0; tt < 4; tt++) {
                unsigned be[2] = {bb[tt].x, bb[tt].y};
                unsigned bo[2] = {bb[tt].z, bb[tt].w};
                mma_f16(d[0][2 * tt],     (unsigned*)&av0, be);
                mma_f16(d[0][2 * tt + 1], (unsigned*)&av0, bo);
                mma_f16(d[1][2 * tt],     (unsigned*)&av1, be);
                mma_f16(d[1][2 * tt + 1], (unsigned*)&av1, bo);
            }
#pragma unroll
            for (int tt = 0; tt < 4; tt++) bb[tt] = nb[tt];
            qn += 1024;
        }
    }

    __syncthreads();
    if (tid < 64) {
        float z = 0.f;
#pragma unroll
        for (int i = 0; i < NCHUNK; i++) z += g_Zpart[i][m0 + tid];
        rzs[tid] = 1.0f / z;
    }
    __syncthreads();

#pragma unroll
    for (int mt = 0; mt < 2; mt++) {
        int rl = wm * 32 + mt * 16 + grp;
        float rz0 = rzs[rl], rz1 = rzs[rl + 8];
        int gi = m0 + rl;
#pragma unroll
        for (int nt = 0; nt < 8; nt++) {
            int gf = wn * 64 + nt * 8 + tig * 2;
            float b0 = sbias[gf], b1 = sbias[gf + 1];
            float v;
            v = fmaf(d[mt][nt][0], rz0, b0);
            out[(size_t)gi * F_OUT + gf]           = v > 0.f ? v : fast_exp(v) - 1.0f;
            v = fmaf(d[mt][nt][1], rz0, b1);
            out[(size_t)gi * F_OUT + gf + 1]       = v > 0.f ? v : fast_exp(v) - 1.0f;
            v = fmaf(d[mt][nt][2], rz1, b0);
            out[(size_t)(gi + 8) * F_OUT + gf]     = v > 0.f ? v : fast_exp(v) - 1.0f;
            v = fmaf(d[mt][nt][3], rz1, b1);
            out[(size_t)(gi + 8) * F_OUT + gf + 1] = v > 0.f ? v : fast_exp(v) - 1.0f;
        }
    }
}

// ---------------- launch ----------------
extern "C" void kernel_launch(void* const* d_in, const int* in_sizes, int n_in,
                              void* d_out, int out_size) {
    const float* x      = (const float*)d_in[0];
    const float* adj    = (const float*)d_in[1];
    const int*   adj_ad = (const int*)d_in[2];
    const float* seq_W  = (const float*)d_in[3];
    const float* f1w    = (const float*)d_in[4];
    const float* f1b    = (const float*)d_in[5];
    const float* f2w    = (const float*)d_in[6];
    const float* f2b    = (const float*)d_in[7];
    const float* bias   = (const float*)d_in[8];
    float* out = (float*)d_out;

    k1_seqfts<<<dim3(8, 64), 256>>>(x, seq_W);
    k1b_repack<<<512, 256>>>();
    k2_fvec<<<N_NODES / 8, 256>>>(f1w, f1b, f2w, f2b);
    k4a_pgen<<<dim3(NCHUNK, 64), 256>>>(adj, adj_ad);
    int write_ri = (out_size >= N_NODES * F_OUT + 2 * N_NODES) ? 1 : 0;
    k4b_ri<<<N_NODES / 256, 256>>>(out + (size_t)N_NODES * F_OUT, write_ri);
    k5_gemm<<<N_NODES / 64, 512>>>(bias, out);
}

// round 16
// speedup vs baseline: 1.2352x; 1.0251x over previous
#include <cuda_runtime.h>
#include <cuda_fp16.h>
#include <cstdint>

#define N_NODES 8192
#define F_IN    1024
#define F_OUT   512
#define NCHUNK  16

// ---------------- device scratch ----------------
__device__ float    g_S [N_NODES * F_OUT];     // seq_fts fp32 (for k2/k1b)
__device__ unsigned g_Bh[(size_t)512 * 32 * 32 * 4];            // 8.4 MB
__device__ unsigned g_Af[(size_t)512 * 512 * 128];              // 134 MB
__device__ float    g_Zpart[NCHUNK][N_NODES];
__device__ int      g_Cpart[NCHUNK][N_NODES];
__device__ float    g_f1[N_NODES];
__device__ float    g_f2[N_NODES];
__device__ unsigned g_f2maxi;                  // ordered-uint encoding of max(f2)

// ---------------- helpers ----------------
__device__ __forceinline__ float fast_exp(float x) {
    float t = x * 1.4426950408889634f;
    t = fminf(fmaxf(t, -126.0f), 126.0f);
    float fi = rintf(t);
    float f  = t - fi;
    float p  =          1.5403530393381609e-4f;
    p = fmaf(p, f, 1.3333558146428443e-3f);
    p = fmaf(p, f, 9.6181291076284772e-3f);
    p = fmaf(p, f, 5.5504108664821580e-2f);
    p = fmaf(p, f, 2.4022650695910071e-1f);
    p = fmaf(p, f, 6.9314718055994531e-1f);
    p = fmaf(p, f, 1.0f);
    int e = (int)fi;
    return p * __int_as_float((e + 127) << 23);
}

__device__ __forceinline__ void mma_f16(float* d, const unsigned* a, const unsigned* b) {
    asm volatile(
        "mma.sync.aligned.m16n8k16.row.col.f32.f16.f16.f32 "
        "{%0,%1,%2,%3}, {%4,%5,%6,%7}, {%8,%9}, {%0,%1,%2,%3};"
        : "+f"(d[0]), "+f"(d[1]), "+f"(d[2]), "+f"(d[3])
        : "r"(a[0]), "r"(a[1]), "r"(a[2]), "r"(a[3]), "r"(b[0]), "r"(b[1]));
}

__device__ __forceinline__ void cp16(void* smem_ptr, const void* gptr) {
    unsigned sa = (unsigned)__cvta_generic_to_shared(smem_ptr);
    asm volatile("cp.async.cg.shared.global [%0], [%1], 16;" :: "r"(sa), "l"(gptr));
}
__device__ __forceinline__ void cp_commit() { asm volatile("cp.async.commit_group;"); }
__device__ __forceinline__ void cp_wait1()  { asm volatile("cp.async.wait_group 1;"); }

__device__ __forceinline__ unsigned h2bits(float lo, float hi) {
    __half2 h = __floats2half2_rn(lo, hi);
    return *(unsigned*)&h;
}

__device__ __forceinline__ unsigned fenc(float v) {
    unsigned b = __float_as_uint(v);
    return (b & 0x80000000u) ? ~b : (b | 0x80000000u);
}
__device__ __forceinline__ float fdec(unsigned e) {
    unsigned b = (e & 0x80000000u) ? (e & 0x7fffffffu) : ~e;
    return __uint_as_float(b);
}

// ---------------- K1: seq_fts = x @ seq_W.T (fp16, BK=64) -------------------
__global__ __launch_bounds__(256) void k1_seqfts(const float* __restrict__ X,
                                                 const float* __restrict__ W) {
    if (blockIdx.x == 0 && blockIdx.y == 0 && threadIdx.x == 0) g_f2maxi = 0u;

    __shared__ unsigned As[128][36];    // 64 halves = 32 uints + 4 pad
    __shared__ unsigned Bs[64][36];
    const int tid = threadIdx.x;
    const int m0 = blockIdx.y * 128;
    const int n0 = blockIdx.x * 64;
    const int warp = tid >> 5, lane = tid & 31;
    const int grp = lane >> 2, tig = lane & 3;
    const int wm = warp & 3, wn = warp >> 2;

    float d[2][4][4];
#pragma unroll
    for (int i = 0; i < 2; i++)
#pragma unroll
        for (int j = 0; j < 4; j++)
#pragma unroll
            for (int q = 0; q < 4; q++) d[i][j][q] = 0.0f;

    for (int k0 = 0; k0 < F_IN; k0 += 64) {
#pragma unroll
        for (int p = 0; p < 8; p++) {      // A: 128 x 64 = 2048 float4
            int idx = tid + p * 256;
            int row = idx >> 4, c16 = idx & 15;
            float4 v = *(const float4*)&X[(size_t)(m0 + row) * F_IN + k0 + c16 * 4];
            *(uint2*)&As[row][c16 * 2] = make_uint2(h2bits(v.x, v.y), h2bits(v.z, v.w));
        }
#pragma unroll
        for (int p = 0; p < 4; p++) {      // B: 64 x 64 = 1024 float4
            int idx = tid + p * 256;
            int row = idx >> 4, c16 = idx & 15;
            float4 v = *(const float4*)&W[(size_t)(n0 + row) * F_IN + k0 + c16 * 4];
            *(uint2*)&Bs[row][c16 * 2] = make_uint2(h2bits(v.x, v.y), h2bits(v.z, v.w));
        }
        __syncthreads();
#pragma unroll
        for (int kt = 0; kt < 4; kt++) {
            unsigned ah[2][4];
#pragma unroll
            for (int mt = 0; mt < 2; mt++) {
                int rb = wm * 32 + mt * 16;
                ah[mt][0] = As[rb + grp][kt * 8 + tig];
                ah[mt][1] = As[rb + grp + 8][kt * 8 + tig];
                ah[mt][2] = As[rb + grp][kt * 8 + tig + 4];
                ah[mt][3] = As[rb + grp + 8][kt * 8 + tig + 4];
            }
            unsigned bh[4][2];
#pragma unroll
            for (int nt = 0; nt < 4; nt++) {
                int cb = wn * 32 + nt * 8;
                bh[nt][0] = Bs[cb + grp][kt * 8 + tig];
                bh[nt][1] = Bs[cb + grp][kt * 8 + tig + 4];
            }
#pragma unroll
            for (int mt = 0; mt < 2; mt++)
#pragma unroll
                for (int nt = 0; nt < 4; nt++)
                    mma_f16(d[mt][nt], ah[mt], bh[nt]);
        }
        __syncthreads();
    }
#pragma unroll
    for (int mt = 0; mt < 2; mt++)
#pragma unroll
        for (int nt = 0; nt < 4; nt++) {
            int r = m0 + wm * 32 + mt * 16 + grp;
            int c = n0 + wn * 32 + nt * 8 + tig * 2;
            size_t i00 = (size_t)r * F_OUT + c;
            size_t i10 = (size_t)(r + 8) * F_OUT + c;
            g_S[i00]     = d[mt][nt][0];
            g_S[i00 + 1] = d[mt][nt][1];
            g_S[i10]     = d[mt][nt][2];
            g_S[i10 + 1] = d[mt][nt][3];
        }
}

// ---------------- K1b: repack S -> fp16 B fragments (g_Bh) ------------------
__global__ __launch_bounds__(256) void k1b_repack() {
    __shared__ float tS[16][520];
    const int k16 = blockIdx.x;
    const int tid = threadIdx.x;
#pragma unroll
    for (int i = 0; i < 8; i++) {
        int idx = tid + i * 256;
        int row = idx >> 7, c4 = (idx & 127) << 2;
        *(float4*)&tS[row][c4] = *(const float4*)&g_S[(size_t)(k16 * 16 + row) * F_OUT + c4];
    }
    __syncthreads();
#pragma unroll
    for (int i = 0; i < 4; i++) {
        int item = tid + i * 256;
        int p = item >> 5, lane = item & 31;
        int gb = lane >> 2, tb = lane & 3;
        int n0 = p * 16 + gb, n1 = n0 + 8;
        int k0 = 2 * tb;
        uint4 q;
        q.x = h2bits(tS[k0][n0],     tS[k0 + 1][n0]);
        q.y = h2bits(tS[k0 + 8][n0], tS[k0 + 9][n0]);
        q.z = h2bits(tS[k0][n1],     tS[k0 + 1][n1]);
        q.w = h2bits(tS[k0 + 8][n1], tS[k0 + 9][n1]);
        ((uint4*)g_Bh)[((size_t)k16 * 32 + p) * 32 + lane] = q;
    }
}

// ---------------- K2: f1/f2 projections + f2max (vectorized) ----------------
__global__ __launch_bounds__(256) void k2_fvec(const float* __restrict__ f1w,
                                               const float* __restrict__ f1b,
                                               const float* __restrict__ f2w,
                                               const float* __restrict__ f2b) {
    __shared__ float bmax[8];
    int warp = threadIdx.x >> 5;
    int row = blockIdx.x * 8 + warp;
    int lane = threadIdx.x & 31;
    const float4* Sr = (const float4*)(g_S + (size_t)row * F_OUT);
    const float4* w1 = (const float4*)f1w;
    const float4* w2 = (const float4*)f2w;
    float s1 = 0.f, s2 = 0.f;
#pragma unroll
    for (int c = 0; c < 4; c++) {
        float4 v = Sr[lane + c * 32];
        float4 a = w1[lane + c * 32];
        float4 b = w2[lane + c * 32];
        s1 = fmaf(v.x, a.x, fmaf(v.y, a.y, fmaf(v.z, a.z, fmaf(v.w, a.w, s1))));
        s2 = fmaf(v.x, b.x, fmaf(v.y, b.y, fmaf(v.z, b.z, fmaf(v.w, b.w, s2))));
    }
#pragma unroll
    for (int o = 16; o > 0; o >>= 1) {
        s1 += __shfl_xor_sync(0xffffffff, s1, o);
        s2 += __shfl_xor_sync(0xffffffff, s2, o);
    }
    float f2v = s2 + f2b[0];
    if (lane == 0) {
        g_f1[row] = s1 + f1b[0];
        g_f2[row] = f2v;
        bmax[warp] = f2v;
    }
    __syncthreads();
    if (threadIdx.x == 0) {
        float m = bmax[0];
#pragma unroll
        for (int i = 1; i < 8; i++) m = fmaxf(m, bmax[i]);
        atomicMax(&g_f2maxi, fenc(m));
    }
}

// ---------------- K4a: pgen + RWR count (fused), grid (16,64) ----------------
__global__ __launch_bounds__(256) void k4a_pgen(const float* __restrict__ adj,
                                                const int* __restrict__ adj_ad) {
    const int tid = threadIdx.x;
    const int warp = tid >> 5, lane = tid & 31;
    const int grp = lane >> 2, tig = lane & 3;
    const int m16 = blockIdx.y * 8 + warp;
    const int r0 = m16 * 16 + grp, r1 = r0 + 8;
    const int kbeg = blockIdx.x * 32;
    const float f2m = fdec(g_f2maxi);
    const float f10 = g_f1[r0], f11 = g_f1[r1];
    float t0 = f10 + f2m; t0 = t0 > 0.f ? t0 : 0.2f * t0;
    float t1 = f11 + f2m; t1 = t1 > 0.f ? t1 : 0.2f * t1;
    const float s0 = t0 + 6.0f, s1 = t1 + 6.0f;
    const float* a0p = adj + (size_t)r0 * N_NODES;
    const float* a1p = adj + (size_t)r1 * N_NODES;
    const int* c0p = adj_ad + (size_t)r0 * N_NODES;
    const int* c1p = adj_ad + (size_t)r1 * N_NODES;
    float z0 = 0.f, z1 = 0.f;
    int cnt0 = 0, cnt1 = 0;
    uint4* dst = (uint4*)g_Af + ((size_t)kbeg * 512 + m16) * 32 + lane;

#define PEXP(f1v, f2v, av, sv) ({ float _l = (f1v) + (f2v); _l = _l > 0.f ? _l : 0.2f * _l; \
                                  fminf(fast_exp(_l + (av) - (sv)), 60000.0f); })
#define CNT2(v) (((v).x == 2 || (v).x == 3) + ((v).y == 2 || (v).y == 3))

    for (int k16 = kbeg; k16 < kbeg + 32; k16++) {
        const int c0 = k16 * 16 + 2 * tig;
        float2 f2a = *(const float2*)&g_f2[c0];
        float2 f2b = *(const float2*)&g_f2[c0 + 8];
        float2 a00 = *(const float2*)(a0p + c0);
        float2 a08 = *(const float2*)(a0p + c0 + 8);
        float2 a10 = *(const float2*)(a1p + c0);
        float2 a18 = *(const float2*)(a1p + c0 + 8);
        int2 q00 = *(const int2*)(c0p + c0);
        int2 q08 = *(const int2*)(c0p + c0 + 8);
        int2 q10 = *(const int2*)(c1p + c0);
        int2 q18 = *(const int2*)(c1p + c0 + 8);
        cnt0 += CNT2(q00) + CNT2(q08);
        cnt1 += CNT2(q10) + CNT2(q18);
        float e00 = PEXP(f10, f2a.x, a00.x, s0);
        float e01 = PEXP(f10, f2a.y, a00.y, s0);
        float e08 = PEXP(f10, f2b.x, a08.x, s0);
        float e09 = PEXP(f10, f2b.y, a08.y, s0);
        float e10 = PEXP(f11, f2a.x, a10.x, s1);
        float e11 = PEXP(f11, f2a.y, a10.y, s1);
        float e18 = PEXP(f11, f2b.x, a18.x, s1);
        float e19 = PEXP(f11, f2b.y, a18.y, s1);
        z0 += (e00 + e01) + (e08 + e09);
        z1 += (e10 + e11) + (e18 + e19);
        uint4 q;
        q.x = h2bits(e00, e01);
        q.y = h2bits(e10, e11);
        q.z = h2bits(e08, e09);
        q.w = h2bits(e18, e19);
        *dst = q;
        dst += 512 * 32;
    }
    z0 += __shfl_xor_sync(0xffffffff, z0, 1);
    z0 += __shfl_xor_sync(0xffffffff, z0, 2);
    z1 += __shfl_xor_sync(0xffffffff, z1, 1);
    z1 += __shfl_xor_sync(0xffffffff, z1, 2);
    cnt0 += __shfl_xor_sync(0xffffffff, cnt0, 1);
    cnt0 += __shfl_xor_sync(0xffffffff, cnt0, 2);
    cnt1 += __shfl_xor_sync(0xffffffff, cnt1, 1);
    cnt1 += __shfl_xor_sync(0xffffffff, cnt1, 2);
    if (tig == 0) {
        g_Zpart[blockIdx.x][r0] = z0;
        g_Zpart[blockIdx.x][r1] = z1;
        g_Cpart[blockIdx.x][r0] = cnt0;
        g_Cpart[blockIdx.x][r1] = cnt1;
    }
}

// ---------------- K4b: RWR finalize ------------------------------------------
__global__ __launch_bounds__(256) void k4b_ri(float* __restrict__ out_ri,
                                              int write_ri) {
    int i = blockIdx.x * 256 + threadIdx.x;
    if (!write_ri || i >= N_NODES) return;
    int c = 0;
#pragma unroll
    for (int p = 0; p < NCHUNK; p++) c += g_Cpart[p][i];
    float k = (float)c;
    float den = 1.0f - 0.25f * k;
    float r0, rn;
    if (den == 0.0f) { r0 = 1.0f; rn = 0.5f; }
    else             { r0 = fabsf(1.0f / den); rn = fabsf(0.5f / den); }
    out_ri[2 * i]     = r0;
    out_ri[2 * i + 1] = rn;
}

// ---------------- K5: GEMM  h = elu(P' @ S / Z' + bias) ---------------------
// Stage = 8 k16 (16KB), 3 stages -> 64 sync points instead of 128.
__global__ __launch_bounds__(512, 1) void k5_gemm(const float* __restrict__ bias,
                                                  float* __restrict__ out) {
    __shared__ unsigned smA[3 * 4096];    // 48 KB
    __shared__ float rzs[64];
    __shared__ float sbias[512];

    const int tid = threadIdx.x;
    const int m0 = blockIdx.x * 64;
    const int warp = tid >> 5, lane = tid & 31;
    const int grp = lane >> 2, tig = lane & 3;
    const int wm = warp >> 3, wn = warp & 7;
    const int mB = m0 >> 4;

    sbias[tid] = bias[tid];

    float d[2][8][4];
#pragma unroll
    for (int mt = 0; mt < 2; mt++)
#pragma unroll
        for (int nt = 0; nt < 8; nt++)
#pragma unroll
            for (int q = 0; q < 4; q++) d[mt][nt][q] = 0.0f;

    const uint4* qB = (const uint4*)g_Bh + (size_t)(4 * wn) * 32 + lane;
    uint4 bb[4], nb[4];
#pragma unroll
    for (int tt = 0; tt < 4; tt++) bb[tt] = qB[tt * 32];
    const uint4* qn = qB + 1024;

    // A staging: 1024 uint4/stage; thread does items tid, tid+512
#define K5_ISSUE(sidx, st) do { \
    _Pragma("unroll") \
    for (int _i = 0; _i < 2; _i++) { \
        int _item = tid + _i * 512; \
        int _ks = _item >> 7, _m16 = (_item >> 5) & 3, _cl = _item & 31; \
        const unsigned* _src = g_Af + (((size_t)((sidx) * 8 + _ks) * 512) + mB + _m16) * 128 + _cl * 4; \
        cp16(&smA[(st) * 4096 + ((_ks * 4 + _m16) * 32 + _cl) * 4], _src); \
    } \
    cp_commit(); \
} while (0)

    K5_ISSUE(0, 0);
    K5_ISSUE(1, 1);

    for (int s = 0; s < 64; s++) {
        const int st = s % 3;
        cp_wait1();
        __syncthreads();
        if (s + 2 < 64) {
            const int st2 = (s + 2) % 3;
            K5_ISSUE(s + 2, st2);
        } else {
            cp_commit();
        }

#pragma unroll
        for (int kk = 0; kk < 8; kk++) {
            if ((kk < 7) || (s < 63)) {
#pragma unroll
                for (int tt = 0; tt < 4; tt++) nb[tt] = qn[tt * 32];
            }
            uint4 av0 = *(const uint4*)&smA[st * 4096 + ((kk * 4 + 2 * wm) * 32 + lane) * 4];
            uint4 av1 = *(const uint4*)&smA[st * 4096 + ((kk * 4 + 2 * wm + 1) * 32 + lane) * 4];
#pragma unroll
            for (int tt = 0; tt < 4; tt++) {
                unsigned be[2] = {bb[tt].x, bb[tt].y};
                unsigned bo[2] = {bb[tt].z, bb[tt].w};
                mma_f16(d[0][2 * tt],     (unsigned*)&av0, be);
                mma_f16(d[0][2 * tt + 1], (unsigned*)&av0, bo);
                mma_f16(d[1][2 * tt],     (unsigned*)&av1, be);
                mma_f16(d[1][2 * tt + 1], (unsigned*)&av1, bo);
            }
#pragma unroll
            for (int tt = 0; tt < 4; tt++) bb[tt] = nb[tt];
            qn += 1024;
        }
    }

    __syncthreads();
    if (tid < 64) {
        float z = 0.f;
#pragma unroll
        for (int i = 0; i < NCHUNK; i++) z += g_Zpart[i][m0 + tid];
        rzs[tid] = 1.0f / z;
    }
    __syncthreads();

#pragma unroll
    for (int mt = 0; mt < 2; mt++) {
        int rl = wm * 32 + mt * 16 + grp;
        float rz0 = rzs[rl], rz1 = rzs[rl + 8];
        int gi = m0 + rl;
#pragma unroll
        for (int nt = 0; nt < 8; nt++) {
            int gf = wn * 64 + nt * 8 + tig * 2;
            float b0 = sbias[gf], b1 = sbias[gf + 1];
            float v;
            v = fmaf(d[mt][nt][0], rz0, b0);
            out[(size_t)gi * F_OUT + gf]           = v > 0.f ? v : fast_exp(v) - 1.0f;
            v = fmaf(d[mt][nt][1], rz0, b1);
            out[(size_t)gi * F_OUT + gf + 1]       = v > 0.f ? v : fast_exp(v) - 1.0f;
            v = fmaf(d[mt][nt][2], rz1, b0);
            out[(size_t)(gi + 8) * F_OUT + gf]     = v > 0.f ? v : fast_exp(v) - 1.0f;
            v = fmaf(d[mt][nt][3], rz1, b1);
            out[(size_t)(gi + 8) * F_OUT + gf + 1] = v > 0.f ? v : fast_exp(v) - 1.0f;
        }
    }
}

// ---------------- launch ----------------
extern "C" void kernel_launch(void* const* d_in, const int* in_sizes, int n_in,
                              void* d_out, int out_size) {
    const float* x      = (const float*)d_in[0];
    const float* adj    = (const float*)d_in[1];
    const int*   adj_ad = (const int*)d_in[2];
    const float* seq_W  = (const float*)d_in[3];
    const float* f1w    = (const float*)d_in[4];
    const float* f1b    = (const float*)d_in[5];
    const float* f2w    = (const float*)d_in[6];
    const float* f2b    = (const float*)d_in[7];
    const float* bias   = (const float*)d_in[8];
    float* out = (float*)d_out;

    k1_seqfts<<<dim3(8, 64), 256>>>(x, seq_W);
    k1b_repack<<<512, 256>>>();
    k2_fvec<<<N_NODES / 8, 256>>>(f1w, f1b, f2w, f2b);
    k4a_pgen<<<dim3(NCHUNK, 64), 256>>>(adj, adj_ad);
    int write_ri = (out_size >= N_NODES * F_OUT + 2 * N_NODES) ? 1 : 0;
    k4b_ri<<<N_NODES / 256, 256>>>(out + (size_t)N_NODES * F_OUT, write_ri);
    k5_gemm<<<N_NODES / 64, 512>>>(bias, out);
}